// round 13
// baseline (speedup 1.0000x reference)
#include <cuda_runtime.h>
#include <cuda_bf16.h>

#define NNODES 100000
#define NEDGES 1600000
#define DIM 64
#define HID 128
#define ODIM 64
#define GEPS 1e-7f
#define BN_EPSC 1e-5f
#define NORM_EPSC 1e-12f

#define SCAN_CHUNK 512
#define NB1 ((NNODES + SCAN_CHUNK - 1) / SCAN_CHUNK)   // 196

// gemm1 dynamic smem layout (floats): sxT[64][132] | sw[64][128] | red_s[128] | red_q[128]
#define G1_SXT   (DIM * 132)
#define G1_SW    (DIM * HID)
#define G1_SMEM_FLOATS (G1_SXT + G1_SW + 2 * HID)
#define G1_SMEM_BYTES  (G1_SMEM_FLOATS * 4)

// gemm2 dynamic smem layout (floats): shT[128][132] | sw2[128][64] | sab[256]
#define G2_SHT   (HID * 132)
#define G2_SW    (HID * ODIM)
#define G2_SMEM_FLOATS (G2_SHT + G2_SW + 2 * HID)
#define G2_SMEM_BYTES  (G2_SMEM_FLOATS * 4)

// packed f32x2 helpers (sm_103a: fma.rn.f32x2 = 2 fp32 FMAs per instruction)
#define FMA2(acc, a, b) \
    asm("fma.rn.f32x2 %0, %1, %2, %0;" : "+l"(acc) : "l"(a), "l"(b))
#define PACK2DUP(out, v) \
    asm("mov.b64 %0, {%1, %1};" : "=l"(out) : "f"(v))
#define UNPACK2(lo, hi, v) \
    asm("mov.b64 {%0, %1}, %2;" : "=f"(lo), "=f"(hi) : "l"(v))

// -------- scratch (device globals; no allocation allowed) --------
__device__ int   g_cnt[NNODES];          // in-degree histogram
__device__ int   g_off[NNODES + 1];      // CSR offsets
__device__ int   g_fill[NNODES];         // running fill pointers (scatter)
__device__ int   g_bsum[256];            // per-chunk sums
__device__ int2  g_epair[NEDGES];        // {edge id, src node} sorted by dst
__device__ float g_x[NNODES * DIM];      // post-MessageNorm features
__device__ float g_hidden[NNODES * HID]; // GEMM1 output (pre-BN)
__device__ float g_bnsum[HID];
__device__ float g_bnsq[HID];

// -------- kernel 0: zero histogram + BN stats --------
__global__ void zero_kernel() {
    int i = blockIdx.x * blockDim.x + threadIdx.x;
    if (i < NNODES) g_cnt[i] = 0;
    if (i < HID) { g_bnsum[i] = 0.f; g_bnsq[i] = 0.f; }
}

// -------- kernel 1: in-degree histogram --------
__global__ void hist_kernel(const int* __restrict__ dst) {
    int e = blockIdx.x * blockDim.x + threadIdx.x;
    if (e < NEDGES) atomicAdd(&g_cnt[__ldg(dst + e)], 1);
}

// -------- kernel 2a: per-chunk sums --------
__global__ void __launch_bounds__(256) scan1_kernel() {
    __shared__ int s[256];
    int b = blockIdx.x, tid = threadIdx.x;
    int base = b * SCAN_CHUNK;
    int i0 = base + 2 * tid, i1 = i0 + 1;
    int c0 = (i0 < NNODES) ? g_cnt[i0] : 0;
    int c1 = (i1 < NNODES) ? g_cnt[i1] : 0;
    s[tid] = c0 + c1;
    __syncthreads();
    #pragma unroll
    for (int st = 128; st; st >>= 1) {
        if (tid < st) s[tid] += s[tid + st];
        __syncthreads();
    }
    if (tid == 0) g_bsum[b] = s[0];
}

// -------- kernel 2b: final offsets; each block derives its own chunk prefix ----
__global__ void __launch_bounds__(256) scan3_kernel() {
    __shared__ int s[256];
    __shared__ int pre[256];
    int b = blockIdx.x, tid = threadIdx.x;

    pre[tid] = (tid < b) ? g_bsum[tid] : 0;
    __syncthreads();
    #pragma unroll
    for (int st = 128; st; st >>= 1) {
        if (tid < st) pre[tid] += pre[tid + st];
        __syncthreads();
    }
    int blk_off = pre[0];
    __syncthreads();

    int base = b * SCAN_CHUNK;
    int i0 = base + 2 * tid, i1 = i0 + 1;
    int c0 = (i0 < NNODES) ? g_cnt[i0] : 0;
    int c1 = (i1 < NNODES) ? g_cnt[i1] : 0;
    int p = c0 + c1;
    s[tid] = p;
    __syncthreads();
    #pragma unroll
    for (int st = 1; st < 256; st <<= 1) {
        int t = (tid >= st) ? s[tid - st] : 0;
        __syncthreads();
        s[tid] += t;
        __syncthreads();
    }
    int excl = blk_off + s[tid] - p;
    if (i0 < NNODES) { g_off[i0] = excl; g_fill[i0] = excl; }
    if (i1 < NNODES) { g_off[i1] = excl + c0; g_fill[i1] = excl + c0; }
    if (b == 0 && tid == 0) g_off[NNODES] = NEDGES;
}

// -------- kernel 3: scatter {edge, src} pairs into CSR order --------
__global__ void scatter_kernel(const int* __restrict__ dst,
                               const int* __restrict__ src) {
    int e = blockIdx.x * blockDim.x + threadIdx.x;
    if (e < NEDGES) {
        int d = __ldg(dst + e);
        int pos = atomicAdd(&g_fill[d], 1);
        g_epair[pos] = make_int2(e, __ldg(src + e));
    }
}

// -------- kernel 4: gather-aggregate + fused MessageNorm --------
__global__ void __launch_bounds__(256) gather_kernel(const float* __restrict__ feats,
                                                     const float* __restrict__ eh,
                                                     const float* __restrict__ scale) {
    int t = blockIdx.x * blockDim.x + threadIdx.x;  // N*16 = 1.6M exactly
    int n = t >> 4;
    int c = (t & 15) << 2;
    int base = __ldg(g_off + n);
    int end  = __ldg(g_off + n + 1);

    float4 num = make_float4(0.f, 0.f, 0.f, 0.f);
    float4 den = make_float4(0.f, 0.f, 0.f, 0.f);
    for (int i = base; i < end; i++) {
        int2 es = __ldg(g_epair + i);
        float4 f  = *(const float4*)(feats + (size_t)es.y * DIM + c);
        float4 ev = __ldg((const float4*)(eh + (size_t)es.x * DIM + c));
        float m0 = fmaxf(f.x + ev.x, 0.f) + GEPS;
        float m1 = fmaxf(f.y + ev.y, 0.f) + GEPS;
        float m2 = fmaxf(f.z + ev.z, 0.f) + GEPS;
        float m3 = fmaxf(f.w + ev.w, 0.f) + GEPS;
        float e0 = __expf(m0), e1 = __expf(m1), e2 = __expf(m2), e3 = __expf(m3);
        den.x += e0; den.y += e1; den.z += e2; den.w += e3;
        num.x += e0 * m0; num.y += e1 * m1; num.z += e2 * m2; num.w += e3 * m3;
    }

    float4 h;
    h.x = den.x > 0.f ? num.x / den.x : 0.f;
    h.y = den.y > 0.f ? num.y / den.y : 0.f;
    h.z = den.z > 0.f ? num.z / den.z : 0.f;
    h.w = den.w > 0.f ? num.w / den.w : 0.f;

    size_t o = (size_t)n * DIM + c;
    float4 f = *(const float4*)(feats + o);
    float hs = h.x * h.x + h.y * h.y + h.z * h.z + h.w * h.w;
    float fs = f.x * f.x + f.y * f.y + f.z * f.z + f.w * f.w;
    #pragma unroll
    for (int off = 8; off; off >>= 1) {
        hs += __shfl_xor_sync(0xffffffffu, hs, off);
        fs += __shfl_xor_sync(0xffffffffu, fs, off);
    }
    float kk = sqrtf(fs) * __ldg(scale) / fmaxf(sqrtf(hs), NORM_EPSC);
    float4 x = make_float4(f.x + h.x * kk, f.y + h.y * kk,
                           f.z + h.z * kk, f.w + h.w * kk);
    *(float4*)(g_x + o) = x;
}

// -------- kernel 5: GEMM1 (x@W1+b1) + BN stats --------
// Dynamic smem: full W1 resident, single sync, straight 64-step mainloop.
__global__ void __launch_bounds__(256) gemm1_kernel(const float* __restrict__ W1,
                                                    const float* __restrict__ b1) {
    extern __shared__ float dyn[];
    float (*sxT)[132] = (float(*)[132])dyn;              // [64][132]
    float (*sw)[HID]  = (float(*)[HID])(dyn + G1_SXT);   // [64][128]
    float* red_s = dyn + G1_SXT + G1_SW;
    float* red_q = red_s + HID;

    int tid = threadIdx.x;
    int m0 = blockIdx.x * 128;

    {
        const float4* wsrc = (const float4*)W1;
        float4* wdst = (float4*)sw;
        #pragma unroll
        for (int p = 0; p < 8; p++) wdst[tid + p * 256] = wsrc[tid + p * 256];
    }
    {
        int hw = tid >> 4;
        int c = (tid & 15) * 4;
        #pragma unroll
        for (int p = 0; p < 8; p++) {
            int r = p * 16 + hw;
            int n = m0 + r;
            float4 v = make_float4(0.f, 0.f, 0.f, 0.f);
            if (n < NNODES) v = *(const float4*)(g_x + (size_t)n * DIM + c);
            sxT[c + 0][r] = v.x;
            sxT[c + 1][r] = v.y;
            sxT[c + 2][r] = v.z;
            sxT[c + 3][r] = v.w;
        }
    }
    if (tid < HID) { red_s[tid] = 0.f; red_q[tid] = 0.f; }
    __syncthreads();

    int ty = tid >> 4;
    int tx = tid & 15;

    unsigned long long acc2[8][4];
    #pragma unroll
    for (int i = 0; i < 8; i++)
        #pragma unroll
        for (int j = 0; j < 4; j++) acc2[i][j] = 0ull;

    #pragma unroll 8
    for (int kk = 0; kk < DIM; kk++) {
        float4 a0 = *(float4*)&sxT[kk][ty * 8];
        float4 a1 = *(float4*)&sxT[kk][ty * 8 + 4];
        double2 bq0 = *(double2*)&sw[kk][tx * 8];
        double2 bq1 = *(double2*)&sw[kk][tx * 8 + 4];
        unsigned long long b2[4];
        b2[0] = __double_as_longlong(bq0.x);
        b2[1] = __double_as_longlong(bq0.y);
        b2[2] = __double_as_longlong(bq1.x);
        b2[3] = __double_as_longlong(bq1.y);
        float a[8] = {a0.x, a0.y, a0.z, a0.w, a1.x, a1.y, a1.z, a1.w};
        #pragma unroll
        for (int i = 0; i < 8; i++) {
            unsigned long long ad;
            PACK2DUP(ad, a[i]);
            FMA2(acc2[i][0], ad, b2[0]);
            FMA2(acc2[i][1], ad, b2[1]);
            FMA2(acc2[i][2], ad, b2[2]);
            FMA2(acc2[i][3], ad, b2[3]);
        }
    }

    float bb[8];
    #pragma unroll
    for (int j = 0; j < 8; j++) bb[j] = __ldg(b1 + tx * 8 + j);
    float ps[8], pq[8];
    #pragma unroll
    for (int j = 0; j < 8; j++) { ps[j] = 0.f; pq[j] = 0.f; }

    #pragma unroll
    for (int i = 0; i < 8; i++) {
        int n = m0 + ty * 8 + i;
        if (n < NNODES) {
            float h[8];
            #pragma unroll
            for (int j2 = 0; j2 < 4; j2++)
                UNPACK2(h[2 * j2], h[2 * j2 + 1], acc2[i][j2]);
            #pragma unroll
            for (int j = 0; j < 8; j++) {
                h[j] += bb[j];
                ps[j] += h[j];
                pq[j] += h[j] * h[j];
            }
            float* dstp = g_hidden + (size_t)n * HID + tx * 8;
            *(float4*)(dstp)     = make_float4(h[0], h[1], h[2], h[3]);
            *(float4*)(dstp + 4) = make_float4(h[4], h[5], h[6], h[7]);
        }
    }
    #pragma unroll
    for (int j = 0; j < 8; j++) {
        atomicAdd(&red_s[tx * 8 + j], ps[j]);
        atomicAdd(&red_q[tx * 8 + j], pq[j]);
    }
    __syncthreads();
    if (tid < HID) {
        atomicAdd(&g_bnsum[tid], red_s[tid]);
        atomicAdd(&g_bnsq[tid], red_q[tid]);
    }
}

// -------- kernel 6: out = relu(bn(hidden)) @ W2 + b2 --------
// Dynamic smem: full hidden tile (BN+ReLU applied) + full W2; 2 syncs total.
__global__ void __launch_bounds__(256) gemm2_kernel(const float* __restrict__ gamma,
                                                    const float* __restrict__ beta,
                                                    const float* __restrict__ W2,
                                                    const float* __restrict__ b2v,
                                                    float* __restrict__ out) {
    extern __shared__ float dyn[];
    float (*shT)[132]  = (float(*)[132])dyn;             // [128][132] (k, node)
    float (*sw2)[ODIM] = (float(*)[ODIM])(dyn + G2_SHT); // [128][64]
    float* sab = dyn + G2_SHT + G2_SW;                   // [256]

    int tid = threadIdx.x;
    int m0 = blockIdx.x * 128;

    if (tid < HID) {
        float mean = g_bnsum[tid] * (1.0f / NNODES);
        float var = g_bnsq[tid] * (1.0f / NNODES) - mean * mean;
        float inv = rsqrtf(var + BN_EPSC);
        float a = __ldg(gamma + tid) * inv;
        sab[tid] = a;
        sab[HID + tid] = __ldg(beta + tid) - mean * a;
    }
    __syncthreads();   // sab ready for staging

    // stage full W2: 8192 floats = 2048 float4 -> 8 per thread
    {
        const float4* wsrc = (const float4*)W2;
        float4* wdst = (float4*)sw2;
        #pragma unroll
        for (int p = 0; p < 8; p++) wdst[tid + p * 256] = wsrc[tid + p * 256];
    }
    // stage full hidden tile with BN+ReLU, transposed: 128 nodes x 128 ch = 4096 float4
    #pragma unroll
    for (int p = 0; p < 16; p++) {
        int flat = p * 256 + tid;
        int r = flat >> 5;          // node row 0..127
        int q = flat & 31;          // float4 index within 128 ch
        int n = m0 + r;
        int ch = q * 4;
        float4 v = make_float4(0.f, 0.f, 0.f, 0.f);
        if (n < NNODES) {
            v = *(const float4*)(g_hidden + (size_t)n * HID + ch);
            v.x = fmaxf(v.x * sab[ch + 0] + sab[HID + ch + 0], 0.f);
            v.y = fmaxf(v.y * sab[ch + 1] + sab[HID + ch + 1], 0.f);
            v.z = fmaxf(v.z * sab[ch + 2] + sab[HID + ch + 2], 0.f);
            v.w = fmaxf(v.w * sab[ch + 3] + sab[HID + ch + 3], 0.f);
        }
        shT[ch + 0][r] = v.x;
        shT[ch + 1][r] = v.y;
        shT[ch + 2][r] = v.z;
        shT[ch + 3][r] = v.w;
    }
    __syncthreads();

    int ty = tid >> 4;
    int tx = tid & 15;

    unsigned long long acc2[8][2];
    #pragma unroll
    for (int i = 0; i < 8; i++) { acc2[i][0] = 0ull; acc2[i][1] = 0ull; }

    #pragma unroll 8
    for (int kk = 0; kk < HID; kk++) {
        float4 a0 = *(float4*)&shT[kk][ty * 8];
        float4 a1 = *(float4*)&shT[kk][ty * 8 + 4];
        double2 bq = *(double2*)&sw2[kk][tx * 4];
        unsigned long long bp0 = __double_as_longlong(bq.x);
        unsigned long long bp1 = __double_as_longlong(bq.y);
        float a[8] = {a0.x, a0.y, a0.z, a0.w, a1.x, a1.y, a1.z, a1.w};
        #pragma unroll
        for (int i = 0; i < 8; i++) {
            unsigned long long ad;
            PACK2DUP(ad, a[i]);
            FMA2(acc2[i][0], ad, bp0);
            FMA2(acc2[i][1], ad, bp1);
        }
    }

    float4 bv = *(const float4*)(b2v + tx * 4);
    #pragma unroll
    for (int i = 0; i < 8; i++) {
        int n = m0 + ty * 8 + i;
        if (n < NNODES) {
            float c0, c1, c2, c3;
            UNPACK2(c0, c1, acc2[i][0]);
            UNPACK2(c2, c3, acc2[i][1]);
            float4 o = make_float4(c0 + bv.x, c1 + bv.y, c2 + bv.z, c3 + bv.w);
            *(float4*)(out + (size_t)n * ODIM + tx * 4) = o;
        }
    }
}

// -------- host launcher --------
extern "C" void kernel_launch(void* const* d_in, const int* in_sizes, int n_in,
                              void* d_out, int out_size) {
    const float *feats = nullptr, *edge_h = nullptr, *W1 = nullptr, *b1 = nullptr;
    const float *gamma = nullptr, *bnb = nullptr, *W2 = nullptr, *b2 = nullptr, *scale = nullptr;
    const int *src = nullptr, *dst = nullptr;
    int nE = 0, nW = 0, nH = 0;
    for (int i = 0; i < n_in; i++) {
        int s = in_sizes[i];
        const void* p = d_in[i];
        if (s == NNODES * DIM) feats = (const float*)p;
        else if (s == NEDGES * DIM) edge_h = (const float*)p;
        else if (s == NEDGES) { if (nE++ == 0) src = (const int*)p; else dst = (const int*)p; }
        else if (s == DIM * HID) { if (nW++ == 0) W1 = (const float*)p; else W2 = (const float*)p; }
        else if (s == HID) {
            if (nH == 0) b1 = (const float*)p;
            else if (nH == 1) gamma = (const float*)p;
            else bnb = (const float*)p;
            nH++;
        }
        else if (s == ODIM) b2 = (const float*)p;
        else if (s == 1) scale = (const float*)p;
    }

    static bool attr_done = false;
    if (!attr_done) {
        cudaFuncSetAttribute(gemm1_kernel,
                             cudaFuncAttributeMaxDynamicSharedMemorySize,
                             G1_SMEM_BYTES);
        cudaFuncSetAttribute(gemm2_kernel,
                             cudaFuncAttributeMaxDynamicSharedMemorySize,
                             G2_SMEM_BYTES);
        attr_done = true;
    }

    zero_kernel<<<(NNODES + 255) / 256, 256>>>();
    hist_kernel<<<(NEDGES + 255) / 256, 256>>>(dst);
    scan1_kernel<<<NB1, 256>>>();
    scan3_kernel<<<NB1, 256>>>();
    scatter_kernel<<<(NEDGES + 255) / 256, 256>>>(dst, src);
    gather_kernel<<<(NNODES * 16) / 256, 256>>>(feats, edge_h, scale);
    gemm1_kernel<<<(NNODES + 127) / 128, 256, G1_SMEM_BYTES>>>(W1, b1);
    gemm2_kernel<<<(NNODES + 127) / 128, 256, G2_SMEM_BYTES>>>(gamma, bnb, W2, b2, (float*)d_out);
}

// round 15
// speedup vs baseline: 1.1147x; 1.1147x over previous
#include <cuda_runtime.h>
#include <cuda_bf16.h>

#define NNODES 100000
#define NEDGES 1600000
#define DIM 64
#define HID 128
#define ODIM 64
#define GEPS 1e-7f
#define BN_EPSC 1e-5f
#define NORM_EPSC 1e-12f

#define SCAN_CHUNK 512
#define NB1 ((NNODES + SCAN_CHUNK - 1) / SCAN_CHUNK)   // 196

// gemm1 dynamic smem layout (floats): sxT[64][132] | sw[64][128] | red_s[128] | red_q[128]
#define G1_SXT   (DIM * 132)
#define G1_SW    (DIM * HID)
#define G1_SMEM_FLOATS (G1_SXT + G1_SW + 2 * HID)
#define G1_SMEM_BYTES  (G1_SMEM_FLOATS * 4)

// packed f32x2 helpers (sm_103a: fma.rn.f32x2 = 2 fp32 FMAs per instruction)
#define FMA2(acc, a, b) \
    asm("fma.rn.f32x2 %0, %1, %2, %0;" : "+l"(acc) : "l"(a), "l"(b))
#define PACK2DUP(out, v) \
    asm("mov.b64 %0, {%1, %1};" : "=l"(out) : "f"(v))
#define UNPACK2(lo, hi, v) \
    asm("mov.b64 {%0, %1}, %2;" : "=f"(lo), "=f"(hi) : "l"(v))

// -------- scratch (device globals; no allocation allowed) --------
__device__ int   g_cnt[NNODES];          // in-degree histogram
__device__ int   g_off[NNODES + 1];      // CSR offsets
__device__ int   g_fill[NNODES];         // running fill pointers (scatter)
__device__ int   g_bsum[256];            // per-chunk sums
__device__ int2  g_epair[NEDGES];        // {edge id, src node} sorted by dst
__device__ float g_x[NNODES * DIM];      // post-MessageNorm features
__device__ float g_hidden[NNODES * HID]; // GEMM1 output (pre-BN)
__device__ float g_bnsum[HID];
__device__ float g_bnsq[HID];

// -------- kernel 0: zero histogram + BN stats --------
__global__ void zero_kernel() {
    int i = blockIdx.x * blockDim.x + threadIdx.x;
    if (i < NNODES) g_cnt[i] = 0;
    if (i < HID) { g_bnsum[i] = 0.f; g_bnsq[i] = 0.f; }
}

// -------- kernel 1: in-degree histogram --------
__global__ void hist_kernel(const int* __restrict__ dst) {
    int e = blockIdx.x * blockDim.x + threadIdx.x;
    if (e < NEDGES) atomicAdd(&g_cnt[__ldg(dst + e)], 1);
}

// -------- kernel 2a: per-chunk sums --------
__global__ void __launch_bounds__(256) scan1_kernel() {
    __shared__ int s[256];
    int b = blockIdx.x, tid = threadIdx.x;
    int base = b * SCAN_CHUNK;
    int i0 = base + 2 * tid, i1 = i0 + 1;
    int c0 = (i0 < NNODES) ? g_cnt[i0] : 0;
    int c1 = (i1 < NNODES) ? g_cnt[i1] : 0;
    s[tid] = c0 + c1;
    __syncthreads();
    #pragma unroll
    for (int st = 128; st; st >>= 1) {
        if (tid < st) s[tid] += s[tid + st];
        __syncthreads();
    }
    if (tid == 0) g_bsum[b] = s[0];
}

// -------- kernel 2b: final offsets; each block derives its own chunk prefix ----
__global__ void __launch_bounds__(256) scan3_kernel() {
    __shared__ int s[256];
    __shared__ int pre[256];
    int b = blockIdx.x, tid = threadIdx.x;

    pre[tid] = (tid < b) ? g_bsum[tid] : 0;
    __syncthreads();
    #pragma unroll
    for (int st = 128; st; st >>= 1) {
        if (tid < st) pre[tid] += pre[tid + st];
        __syncthreads();
    }
    int blk_off = pre[0];
    __syncthreads();

    int base = b * SCAN_CHUNK;
    int i0 = base + 2 * tid, i1 = i0 + 1;
    int c0 = (i0 < NNODES) ? g_cnt[i0] : 0;
    int c1 = (i1 < NNODES) ? g_cnt[i1] : 0;
    int p = c0 + c1;
    s[tid] = p;
    __syncthreads();
    #pragma unroll
    for (int st = 1; st < 256; st <<= 1) {
        int t = (tid >= st) ? s[tid - st] : 0;
        __syncthreads();
        s[tid] += t;
        __syncthreads();
    }
    int excl = blk_off + s[tid] - p;
    if (i0 < NNODES) { g_off[i0] = excl; g_fill[i0] = excl; }
    if (i1 < NNODES) { g_off[i1] = excl + c0; g_fill[i1] = excl + c0; }
    if (b == 0 && tid == 0) g_off[NNODES] = NEDGES;
}

// -------- kernel 3: scatter {edge, src} pairs into CSR order --------
__global__ void scatter_kernel(const int* __restrict__ dst,
                               const int* __restrict__ src) {
    int e = blockIdx.x * blockDim.x + threadIdx.x;
    if (e < NEDGES) {
        int d = __ldg(dst + e);
        int pos = atomicAdd(&g_fill[d], 1);
        g_epair[pos] = make_int2(e, __ldg(src + e));
    }
}

// -------- kernel 4: gather-aggregate + fused MessageNorm --------
// eh stream loaded with __ldcs (read-once, evict-first) to protect the
// L2-resident feats / g_epair working sets.
__global__ void __launch_bounds__(256) gather_kernel(const float* __restrict__ feats,
                                                     const float* __restrict__ eh,
                                                     const float* __restrict__ scale) {
    int t = blockIdx.x * blockDim.x + threadIdx.x;  // N*16 = 1.6M exactly
    int n = t >> 4;
    int c = (t & 15) << 2;
    int base = __ldg(g_off + n);
    int end  = __ldg(g_off + n + 1);

    float4 num = make_float4(0.f, 0.f, 0.f, 0.f);
    float4 den = make_float4(0.f, 0.f, 0.f, 0.f);
    for (int i = base; i < end; i++) {
        int2 es = __ldg(g_epair + i);
        float4 f  = *(const float4*)(feats + (size_t)es.y * DIM + c);
        float4 ev = __ldcs((const float4*)(eh + (size_t)es.x * DIM + c));
        float m0 = fmaxf(f.x + ev.x, 0.f) + GEPS;
        float m1 = fmaxf(f.y + ev.y, 0.f) + GEPS;
        float m2 = fmaxf(f.z + ev.z, 0.f) + GEPS;
        float m3 = fmaxf(f.w + ev.w, 0.f) + GEPS;
        float e0 = __expf(m0), e1 = __expf(m1), e2 = __expf(m2), e3 = __expf(m3);
        den.x += e0; den.y += e1; den.z += e2; den.w += e3;
        num.x += e0 * m0; num.y += e1 * m1; num.z += e2 * m2; num.w += e3 * m3;
    }

    float4 h;
    h.x = den.x > 0.f ? num.x / den.x : 0.f;
    h.y = den.y > 0.f ? num.y / den.y : 0.f;
    h.z = den.z > 0.f ? num.z / den.z : 0.f;
    h.w = den.w > 0.f ? num.w / den.w : 0.f;

    size_t o = (size_t)n * DIM + c;
    float4 f = *(const float4*)(feats + o);
    float hs = h.x * h.x + h.y * h.y + h.z * h.z + h.w * h.w;
    float fs = f.x * f.x + f.y * f.y + f.z * f.z + f.w * f.w;
    #pragma unroll
    for (int off = 8; off; off >>= 1) {
        hs += __shfl_xor_sync(0xffffffffu, hs, off);
        fs += __shfl_xor_sync(0xffffffffu, fs, off);
    }
    float kk = sqrtf(fs) * __ldg(scale) / fmaxf(sqrtf(hs), NORM_EPSC);
    float4 x = make_float4(f.x + h.x * kk, f.y + h.y * kk,
                           f.z + h.z * kk, f.w + h.w * kk);
    *(float4*)(g_x + o) = x;
}

// -------- kernel 5: GEMM1 (x@W1+b1) + BN stats --------
// Dynamic smem: full W1 resident, single sync, straight 64-step mainloop.
__global__ void __launch_bounds__(256) gemm1_kernel(const float* __restrict__ W1,
                                                    const float* __restrict__ b1) {
    extern __shared__ float dyn[];
    float (*sxT)[132] = (float(*)[132])dyn;              // [64][132]
    float (*sw)[HID]  = (float(*)[HID])(dyn + G1_SXT);   // [64][128]
    float* red_s = dyn + G1_SXT + G1_SW;
    float* red_q = red_s + HID;

    int tid = threadIdx.x;
    int m0 = blockIdx.x * 128;

    {
        const float4* wsrc = (const float4*)W1;
        float4* wdst = (float4*)sw;
        #pragma unroll
        for (int p = 0; p < 8; p++) wdst[tid + p * 256] = wsrc[tid + p * 256];
    }
    {
        int hw = tid >> 4;
        int c = (tid & 15) * 4;
        #pragma unroll
        for (int p = 0; p < 8; p++) {
            int r = p * 16 + hw;
            int n = m0 + r;
            float4 v = make_float4(0.f, 0.f, 0.f, 0.f);
            if (n < NNODES) v = *(const float4*)(g_x + (size_t)n * DIM + c);
            sxT[c + 0][r] = v.x;
            sxT[c + 1][r] = v.y;
            sxT[c + 2][r] = v.z;
            sxT[c + 3][r] = v.w;
        }
    }
    if (tid < HID) { red_s[tid] = 0.f; red_q[tid] = 0.f; }
    __syncthreads();

    int ty = tid >> 4;
    int tx = tid & 15;

    unsigned long long acc2[8][4];
    #pragma unroll
    for (int i = 0; i < 8; i++)
        #pragma unroll
        for (int j = 0; j < 4; j++) acc2[i][j] = 0ull;

    #pragma unroll 8
    for (int kk = 0; kk < DIM; kk++) {
        float4 a0 = *(float4*)&sxT[kk][ty * 8];
        float4 a1 = *(float4*)&sxT[kk][ty * 8 + 4];
        double2 bq0 = *(double2*)&sw[kk][tx * 8];
        double2 bq1 = *(double2*)&sw[kk][tx * 8 + 4];
        unsigned long long b2[4];
        b2[0] = __double_as_longlong(bq0.x);
        b2[1] = __double_as_longlong(bq0.y);
        b2[2] = __double_as_longlong(bq1.x);
        b2[3] = __double_as_longlong(bq1.y);
        float a[8] = {a0.x, a0.y, a0.z, a0.w, a1.x, a1.y, a1.z, a1.w};
        #pragma unroll
        for (int i = 0; i < 8; i++) {
            unsigned long long ad;
            PACK2DUP(ad, a[i]);
            FMA2(acc2[i][0], ad, b2[0]);
            FMA2(acc2[i][1], ad, b2[1]);
            FMA2(acc2[i][2], ad, b2[2]);
            FMA2(acc2[i][3], ad, b2[3]);
        }
    }

    float bb[8];
    #pragma unroll
    for (int j = 0; j < 8; j++) bb[j] = __ldg(b1 + tx * 8 + j);
    float ps[8], pq[8];
    #pragma unroll
    for (int j = 0; j < 8; j++) { ps[j] = 0.f; pq[j] = 0.f; }

    #pragma unroll
    for (int i = 0; i < 8; i++) {
        int n = m0 + ty * 8 + i;
        if (n < NNODES) {
            float h[8];
            #pragma unroll
            for (int j2 = 0; j2 < 4; j2++)
                UNPACK2(h[2 * j2], h[2 * j2 + 1], acc2[i][j2]);
            #pragma unroll
            for (int j = 0; j < 8; j++) {
                h[j] += bb[j];
                ps[j] += h[j];
                pq[j] += h[j] * h[j];
            }
            float* dstp = g_hidden + (size_t)n * HID + tx * 8;
            *(float4*)(dstp)     = make_float4(h[0], h[1], h[2], h[3]);
            *(float4*)(dstp + 4) = make_float4(h[4], h[5], h[6], h[7]);
        }
    }
    #pragma unroll
    for (int j = 0; j < 8; j++) {
        atomicAdd(&red_s[tx * 8 + j], ps[j]);
        atomicAdd(&red_q[tx * 8 + j], pq[j]);
    }
    __syncthreads();
    if (tid < HID) {
        atomicAdd(&g_bnsum[tid], red_s[tid]);
        atomicAdd(&g_bnsq[tid], red_q[tid]);
    }
}

// -------- kernel 6: out = relu(bn(hidden)) @ W2 + b2 (chunked; BN affine in-block)
__global__ void __launch_bounds__(256) gemm2_kernel(const float* __restrict__ gamma,
                                                    const float* __restrict__ beta,
                                                    const float* __restrict__ W2,
                                                    const float* __restrict__ b2v,
                                                    float* __restrict__ out) {
    __shared__ float shT[32][132];
    __shared__ float sw2[32][ODIM];
    __shared__ float sab[2 * HID];

    int tid = threadIdx.x;
    int m0 = blockIdx.x * 128;

    if (tid < HID) {
        float mean = g_bnsum[tid] * (1.0f / NNODES);
        float var = g_bnsq[tid] * (1.0f / NNODES) - mean * mean;
        float inv = rsqrtf(var + BN_EPSC);
        float a = __ldg(gamma + tid) * inv;
        sab[tid] = a;
        sab[HID + tid] = __ldg(beta + tid) - mean * a;
    }

    int ty = tid >> 4;
    int tx = tid & 15;

    unsigned long long acc2[8][2];
    #pragma unroll
    for (int i = 0; i < 8; i++) { acc2[i][0] = 0ull; acc2[i][1] = 0ull; }

    #pragma unroll
    for (int kc = 0; kc < 4; kc++) {
        int k0 = kc * 32;
        __syncthreads();
        const float4* wsrc = (const float4*)(W2 + (size_t)k0 * ODIM);
        ((float4*)sw2)[tid] = wsrc[tid];
        ((float4*)sw2)[tid + 256] = wsrc[tid + 256];
        #pragma unroll
        for (int p = 0; p < 4; p++) {
            int flat = p * 256 + tid;
            int r = flat >> 3;
            int q = flat & 7;
            int n = m0 + r;
            int ch = k0 + q * 4;
            float4 v = make_float4(0.f, 0.f, 0.f, 0.f);
            if (n < NNODES) {
                v = *(const float4*)(g_hidden + (size_t)n * HID + ch);
                v.x = fmaxf(v.x * sab[ch + 0] + sab[HID + ch + 0], 0.f);
                v.y = fmaxf(v.y * sab[ch + 1] + sab[HID + ch + 1], 0.f);
                v.z = fmaxf(v.z * sab[ch + 2] + sab[HID + ch + 2], 0.f);
                v.w = fmaxf(v.w * sab[ch + 3] + sab[HID + ch + 3], 0.f);
            }
            shT[q * 4 + 0][r] = v.x;
            shT[q * 4 + 1][r] = v.y;
            shT[q * 4 + 2][r] = v.z;
            shT[q * 4 + 3][r] = v.w;
        }
        __syncthreads();
        #pragma unroll
        for (int kk = 0; kk < 32; kk++) {
            float4 a0 = *(float4*)&shT[kk][ty * 8];
            float4 a1 = *(float4*)&shT[kk][ty * 8 + 4];
            double2 bq = *(double2*)&sw2[kk][tx * 4];
            unsigned long long bp0 = __double_as_longlong(bq.x);
            unsigned long long bp1 = __double_as_longlong(bq.y);
            float a[8] = {a0.x, a0.y, a0.z, a0.w, a1.x, a1.y, a1.z, a1.w};
            #pragma unroll
            for (int i = 0; i < 8; i++) {
                unsigned long long ad;
                PACK2DUP(ad, a[i]);
                FMA2(acc2[i][0], ad, bp0);
                FMA2(acc2[i][1], ad, bp1);
            }
        }
    }

    float4 bv = *(const float4*)(b2v + tx * 4);
    #pragma unroll
    for (int i = 0; i < 8; i++) {
        int n = m0 + ty * 8 + i;
        if (n < NNODES) {
            float c0, c1, c2, c3;
            UNPACK2(c0, c1, acc2[i][0]);
            UNPACK2(c2, c3, acc2[i][1]);
            float4 o = make_float4(c0 + bv.x, c1 + bv.y, c2 + bv.z, c3 + bv.w);
            *(float4*)(out + (size_t)n * ODIM + tx * 4) = o;
        }
    }
}

// -------- host launcher --------
extern "C" void kernel_launch(void* const* d_in, const int* in_sizes, int n_in,
                              void* d_out, int out_size) {
    const float *feats = nullptr, *edge_h = nullptr, *W1 = nullptr, *b1 = nullptr;
    const float *gamma = nullptr, *bnb = nullptr, *W2 = nullptr, *b2 = nullptr, *scale = nullptr;
    const int *src = nullptr, *dst = nullptr;
    int nE = 0, nW = 0, nH = 0;
    for (int i = 0; i < n_in; i++) {
        int s = in_sizes[i];
        const void* p = d_in[i];
        if (s == NNODES * DIM) feats = (const float*)p;
        else if (s == NEDGES * DIM) edge_h = (const float*)p;
        else if (s == NEDGES) { if (nE++ == 0) src = (const int*)p; else dst = (const int*)p; }
        else if (s == DIM * HID) { if (nW++ == 0) W1 = (const float*)p; else W2 = (const float*)p; }
        else if (s == HID) {
            if (nH == 0) b1 = (const float*)p;
            else if (nH == 1) gamma = (const float*)p;
            else bnb = (const float*)p;
            nH++;
        }
        else if (s == ODIM) b2 = (const float*)p;
        else if (s == 1) scale = (const float*)p;
    }

    static bool attr_done = false;
    if (!attr_done) {
        cudaFuncSetAttribute(gemm1_kernel,
                             cudaFuncAttributeMaxDynamicSharedMemorySize,
                             G1_SMEM_BYTES);
        attr_done = true;
    }

    zero_kernel<<<(NNODES + 255) / 256, 256>>>();
    hist_kernel<<<(NEDGES + 255) / 256, 256>>>(dst);
    scan1_kernel<<<NB1, 256>>>();
    scan3_kernel<<<NB1, 256>>>();
    scatter_kernel<<<(NEDGES + 255) / 256, 256>>>(dst, src);
    gather_kernel<<<(NNODES * 16) / 256, 256>>>(feats, edge_h, scale);
    gemm1_kernel<<<(NNODES + 127) / 128, 256, G1_SMEM_BYTES>>>(W1, b1);
    gemm2_kernel<<<(NNODES + 127) / 128, 256>>>(gamma, bnb, W2, b2, (float*)d_out);
}

// round 16
// speedup vs baseline: 1.1187x; 1.0035x over previous
#include <cuda_runtime.h>
#include <cuda_bf16.h>

#define NNODES 100000
#define NEDGES 1600000
#define DIM 64
#define HID 128
#define ODIM 64
#define GEPS 1e-7f
#define BN_EPSC 1e-5f
#define NORM_EPSC 1e-12f

#define SCAN_CHUNK 512
#define NB1 ((NNODES + SCAN_CHUNK - 1) / SCAN_CHUNK)   // 196

// gemm1 dynamic smem layout (floats): sxT[64][132] | sw[64][128] | red_s[128] | red_q[128]
#define G1_SXT   (DIM * 132)
#define G1_SW    (DIM * HID)
#define G1_SMEM_FLOATS (G1_SXT + G1_SW + 2 * HID)
#define G1_SMEM_BYTES  (G1_SMEM_FLOATS * 4)

// packed f32x2 helpers (sm_103a: fma.rn.f32x2 = 2 fp32 FMAs per instruction)
#define FMA2(acc, a, b) \
    asm("fma.rn.f32x2 %0, %1, %2, %0;" : "+l"(acc) : "l"(a), "l"(b))
#define PACK2DUP(out, v) \
    asm("mov.b64 %0, {%1, %1};" : "=l"(out) : "f"(v))
#define UNPACK2(lo, hi, v) \
    asm("mov.b64 {%0, %1}, %2;" : "=f"(lo), "=f"(hi) : "l"(v))

// -------- scratch (device globals; no allocation allowed) --------
__device__ int   g_cnt[NNODES];          // in-degree histogram
__device__ int   g_off[NNODES + 1];      // CSR offsets
__device__ int   g_fill[NNODES];         // running fill pointers (scatter)
__device__ int   g_bsum[256];            // per-chunk sums
__device__ int2  g_epair[NEDGES];        // {edge id, src node} sorted by dst
__device__ float g_x[NNODES * DIM];      // post-MessageNorm features
__device__ float g_hidden[NNODES * HID]; // GEMM1 output (pre-BN)
__device__ float g_bnsum[HID];
__device__ float g_bnsq[HID];

// -------- kernel 0: zero histogram + BN stats --------
__global__ void zero_kernel() {
    int i = blockIdx.x * blockDim.x + threadIdx.x;
    if (i < NNODES) g_cnt[i] = 0;
    if (i < HID) { g_bnsum[i] = 0.f; g_bnsq[i] = 0.f; }
}

// -------- kernel 1: in-degree histogram (4 edges per thread via int4) --------
__global__ void hist_kernel(const int* __restrict__ dst) {
    int t = blockIdx.x * blockDim.x + threadIdx.x;   // NEDGES/4 = 400k exactly
    int e = t * 4;
    if (e < NEDGES) {
        int4 d4 = *(const int4*)(dst + e);
        atomicAdd(&g_cnt[d4.x], 1);
        atomicAdd(&g_cnt[d4.y], 1);
        atomicAdd(&g_cnt[d4.z], 1);
        atomicAdd(&g_cnt[d4.w], 1);
    }
}

// -------- kernel 2a: per-chunk sums --------
__global__ void __launch_bounds__(256) scan1_kernel() {
    __shared__ int s[256];
    int b = blockIdx.x, tid = threadIdx.x;
    int base = b * SCAN_CHUNK;
    int i0 = base + 2 * tid, i1 = i0 + 1;
    int c0 = (i0 < NNODES) ? g_cnt[i0] : 0;
    int c1 = (i1 < NNODES) ? g_cnt[i1] : 0;
    s[tid] = c0 + c1;
    __syncthreads();
    #pragma unroll
    for (int st = 128; st; st >>= 1) {
        if (tid < st) s[tid] += s[tid + st];
        __syncthreads();
    }
    if (tid == 0) g_bsum[b] = s[0];
}

// -------- kernel 2b: final offsets; each block derives its own chunk prefix ----
__global__ void __launch_bounds__(256) scan3_kernel() {
    __shared__ int s[256];
    __shared__ int pre[256];
    int b = blockIdx.x, tid = threadIdx.x;

    pre[tid] = (tid < b) ? g_bsum[tid] : 0;
    __syncthreads();
    #pragma unroll
    for (int st = 128; st; st >>= 1) {
        if (tid < st) pre[tid] += pre[tid + st];
        __syncthreads();
    }
    int blk_off = pre[0];
    __syncthreads();

    int base = b * SCAN_CHUNK;
    int i0 = base + 2 * tid, i1 = i0 + 1;
    int c0 = (i0 < NNODES) ? g_cnt[i0] : 0;
    int c1 = (i1 < NNODES) ? g_cnt[i1] : 0;
    int p = c0 + c1;
    s[tid] = p;
    __syncthreads();
    #pragma unroll
    for (int st = 1; st < 256; st <<= 1) {
        int t = (tid >= st) ? s[tid - st] : 0;
        __syncthreads();
        s[tid] += t;
        __syncthreads();
    }
    int excl = blk_off + s[tid] - p;
    if (i0 < NNODES) { g_off[i0] = excl; g_fill[i0] = excl; }
    if (i1 < NNODES) { g_off[i1] = excl + c0; g_fill[i1] = excl + c0; }
    if (b == 0 && tid == 0) g_off[NNODES] = NEDGES;
}

// -------- kernel 3: scatter {edge, src} pairs (2 edges per thread) --------
__global__ void scatter_kernel(const int* __restrict__ dst,
                               const int* __restrict__ src) {
    int t = blockIdx.x * blockDim.x + threadIdx.x;   // NEDGES/2 = 800k exactly
    int e = t * 2;
    if (e < NEDGES) {
        int2 d2 = *(const int2*)(dst + e);
        int2 s2 = *(const int2*)(src + e);
        int p0 = atomicAdd(&g_fill[d2.x], 1);
        int p1 = atomicAdd(&g_fill[d2.y], 1);
        g_epair[p0] = make_int2(e, s2.x);
        g_epair[p1] = make_int2(e + 1, s2.y);
    }
}

// -------- kernel 4: gather-aggregate + fused MessageNorm --------
// eh stream loaded with __ldcs (read-once, evict-first) to protect the
// L2-resident feats / g_epair working sets.
__global__ void __launch_bounds__(256) gather_kernel(const float* __restrict__ feats,
                                                     const float* __restrict__ eh,
                                                     const float* __restrict__ scale) {
    int t = blockIdx.x * blockDim.x + threadIdx.x;  // N*16 = 1.6M exactly
    int n = t >> 4;
    int c = (t & 15) << 2;
    int base = __ldg(g_off + n);
    int end  = __ldg(g_off + n + 1);

    float4 num = make_float4(0.f, 0.f, 0.f, 0.f);
    float4 den = make_float4(0.f, 0.f, 0.f, 0.f);
    for (int i = base; i < end; i++) {
        int2 es = __ldg(g_epair + i);
        float4 f  = *(const float4*)(feats + (size_t)es.y * DIM + c);
        float4 ev = __ldcs((const float4*)(eh + (size_t)es.x * DIM + c));
        float m0 = fmaxf(f.x + ev.x, 0.f) + GEPS;
        float m1 = fmaxf(f.y + ev.y, 0.f) + GEPS;
        float m2 = fmaxf(f.z + ev.z, 0.f) + GEPS;
        float m3 = fmaxf(f.w + ev.w, 0.f) + GEPS;
        float e0 = __expf(m0), e1 = __expf(m1), e2 = __expf(m2), e3 = __expf(m3);
        den.x += e0; den.y += e1; den.z += e2; den.w += e3;
        num.x += e0 * m0; num.y += e1 * m1; num.z += e2 * m2; num.w += e3 * m3;
    }

    float4 h;
    h.x = den.x > 0.f ? num.x / den.x : 0.f;
    h.y = den.y > 0.f ? num.y / den.y : 0.f;
    h.z = den.z > 0.f ? num.z / den.z : 0.f;
    h.w = den.w > 0.f ? num.w / den.w : 0.f;

    size_t o = (size_t)n * DIM + c;
    float4 f = *(const float4*)(feats + o);
    float hs = h.x * h.x + h.y * h.y + h.z * h.z + h.w * h.w;
    float fs = f.x * f.x + f.y * f.y + f.z * f.z + f.w * f.w;
    #pragma unroll
    for (int off = 8; off; off >>= 1) {
        hs += __shfl_xor_sync(0xffffffffu, hs, off);
        fs += __shfl_xor_sync(0xffffffffu, fs, off);
    }
    float kk = sqrtf(fs) * __ldg(scale) / fmaxf(sqrtf(hs), NORM_EPSC);
    float4 x = make_float4(f.x + h.x * kk, f.y + h.y * kk,
                           f.z + h.z * kk, f.w + h.w * kk);
    *(float4*)(g_x + o) = x;
}

// -------- kernel 5: GEMM1 (x@W1+b1) + BN stats --------
// Dynamic smem: full W1 resident, single sync, straight 64-step mainloop.
__global__ void __launch_bounds__(256) gemm1_kernel(const float* __restrict__ W1,
                                                    const float* __restrict__ b1) {
    extern __shared__ float dyn[];
    float (*sxT)[132] = (float(*)[132])dyn;              // [64][132]
    float (*sw)[HID]  = (float(*)[HID])(dyn + G1_SXT);   // [64][128]
    float* red_s = dyn + G1_SXT + G1_SW;
    float* red_q = red_s + HID;

    int tid = threadIdx.x;
    int m0 = blockIdx.x * 128;

    {
        const float4* wsrc = (const float4*)W1;
        float4* wdst = (float4*)sw;
        #pragma unroll
        for (int p = 0; p < 8; p++) wdst[tid + p * 256] = wsrc[tid + p * 256];
    }
    {
        int hw = tid >> 4;
        int c = (tid & 15) * 4;
        #pragma unroll
        for (int p = 0; p < 8; p++) {
            int r = p * 16 + hw;
            int n = m0 + r;
            float4 v = make_float4(0.f, 0.f, 0.f, 0.f);
            if (n < NNODES) v = *(const float4*)(g_x + (size_t)n * DIM + c);
            sxT[c + 0][r] = v.x;
            sxT[c + 1][r] = v.y;
            sxT[c + 2][r] = v.z;
            sxT[c + 3][r] = v.w;
        }
    }
    if (tid < HID) { red_s[tid] = 0.f; red_q[tid] = 0.f; }
    __syncthreads();

    int ty = tid >> 4;
    int tx = tid & 15;

    unsigned long long acc2[8][4];
    #pragma unroll
    for (int i = 0; i < 8; i++)
        #pragma unroll
        for (int j = 0; j < 4; j++) acc2[i][j] = 0ull;

    #pragma unroll 8
    for (int kk = 0; kk < DIM; kk++) {
        float4 a0 = *(float4*)&sxT[kk][ty * 8];
        float4 a1 = *(float4*)&sxT[kk][ty * 8 + 4];
        double2 bq0 = *(double2*)&sw[kk][tx * 8];
        double2 bq1 = *(double2*)&sw[kk][tx * 8 + 4];
        unsigned long long b2[4];
        b2[0] = __double_as_longlong(bq0.x);
        b2[1] = __double_as_longlong(bq0.y);
        b2[2] = __double_as_longlong(bq1.x);
        b2[3] = __double_as_longlong(bq1.y);
        float a[8] = {a0.x, a0.y, a0.z, a0.w, a1.x, a1.y, a1.z, a1.w};
        #pragma unroll
        for (int i = 0; i < 8; i++) {
            unsigned long long ad;
            PACK2DUP(ad, a[i]);
            FMA2(acc2[i][0], ad, b2[0]);
            FMA2(acc2[i][1], ad, b2[1]);
            FMA2(acc2[i][2], ad, b2[2]);
            FMA2(acc2[i][3], ad, b2[3]);
        }
    }

    float bb[8];
    #pragma unroll
    for (int j = 0; j < 8; j++) bb[j] = __ldg(b1 + tx * 8 + j);
    float ps[8], pq[8];
    #pragma unroll
    for (int j = 0; j < 8; j++) { ps[j] = 0.f; pq[j] = 0.f; }

    #pragma unroll
    for (int i = 0; i < 8; i++) {
        int n = m0 + ty * 8 + i;
        if (n < NNODES) {
            float h[8];
            #pragma unroll
            for (int j2 = 0; j2 < 4; j2++)
                UNPACK2(h[2 * j2], h[2 * j2 + 1], acc2[i][j2]);
            #pragma unroll
            for (int j = 0; j < 8; j++) {
                h[j] += bb[j];
                ps[j] += h[j];
                pq[j] += h[j] * h[j];
            }
            float* dstp = g_hidden + (size_t)n * HID + tx * 8;
            *(float4*)(dstp)     = make_float4(h[0], h[1], h[2], h[3]);
            *(float4*)(dstp + 4) = make_float4(h[4], h[5], h[6], h[7]);
        }
    }
    #pragma unroll
    for (int j = 0; j < 8; j++) {
        atomicAdd(&red_s[tx * 8 + j], ps[j]);
        atomicAdd(&red_q[tx * 8 + j], pq[j]);
    }
    __syncthreads();
    if (tid < HID) {
        atomicAdd(&g_bnsum[tid], red_s[tid]);
        atomicAdd(&g_bnsq[tid], red_q[tid]);
    }
}

// -------- kernel 6: out = relu(bn(hidden)) @ W2 + b2 (chunked; BN affine in-block)
__global__ void __launch_bounds__(256) gemm2_kernel(const float* __restrict__ gamma,
                                                    const float* __restrict__ beta,
                                                    const float* __restrict__ W2,
                                                    const float* __restrict__ b2v,
                                                    float* __restrict__ out) {
    __shared__ float shT[32][132];
    __shared__ float sw2[32][ODIM];
    __shared__ float sab[2 * HID];

    int tid = threadIdx.x;
    int m0 = blockIdx.x * 128;

    if (tid < HID) {
        float mean = g_bnsum[tid] * (1.0f / NNODES);
        float var = g_bnsq[tid] * (1.0f / NNODES) - mean * mean;
        float inv = rsqrtf(var + BN_EPSC);
        float a = __ldg(gamma + tid) * inv;
        sab[tid] = a;
        sab[HID + tid] = __ldg(beta + tid) - mean * a;
    }

    int ty = tid >> 4;
    int tx = tid & 15;

    unsigned long long acc2[8][2];
    #pragma unroll
    for (int i = 0; i < 8; i++) { acc2[i][0] = 0ull; acc2[i][1] = 0ull; }

    #pragma unroll
    for (int kc = 0; kc < 4; kc++) {
        int k0 = kc * 32;
        __syncthreads();
        const float4* wsrc = (const float4*)(W2 + (size_t)k0 * ODIM);
        ((float4*)sw2)[tid] = wsrc[tid];
        ((float4*)sw2)[tid + 256] = wsrc[tid + 256];
        #pragma unroll
        for (int p = 0; p < 4; p++) {
            int flat = p * 256 + tid;
            int r = flat >> 3;
            int q = flat & 7;
            int n = m0 + r;
            int ch = k0 + q * 4;
            float4 v = make_float4(0.f, 0.f, 0.f, 0.f);
            if (n < NNODES) {
                v = *(const float4*)(g_hidden + (size_t)n * HID + ch);
                v.x = fmaxf(v.x * sab[ch + 0] + sab[HID + ch + 0], 0.f);
                v.y = fmaxf(v.y * sab[ch + 1] + sab[HID + ch + 1], 0.f);
                v.z = fmaxf(v.z * sab[ch + 2] + sab[HID + ch + 2], 0.f);
                v.w = fmaxf(v.w * sab[ch + 3] + sab[HID + ch + 3], 0.f);
            }
            shT[q * 4 + 0][r] = v.x;
            shT[q * 4 + 1][r] = v.y;
            shT[q * 4 + 2][r] = v.z;
            shT[q * 4 + 3][r] = v.w;
        }
        __syncthreads();
        #pragma unroll
        for (int kk = 0; kk < 32; kk++) {
            float4 a0 = *(float4*)&shT[kk][ty * 8];
            float4 a1 = *(float4*)&shT[kk][ty * 8 + 4];
            double2 bq = *(double2*)&sw2[kk][tx * 4];
            unsigned long long bp0 = __double_as_longlong(bq.x);
            unsigned long long bp1 = __double_as_longlong(bq.y);
            float a[8] = {a0.x, a0.y, a0.z, a0.w, a1.x, a1.y, a1.z, a1.w};
            #pragma unroll
            for (int i = 0; i < 8; i++) {
                unsigned long long ad;
                PACK2DUP(ad, a[i]);
                FMA2(acc2[i][0], ad, bp0);
                FMA2(acc2[i][1], ad, bp1);
            }
        }
    }

    float4 bv = *(const float4*)(b2v + tx * 4);
    #pragma unroll
    for (int i = 0; i < 8; i++) {
        int n = m0 + ty * 8 + i;
        if (n < NNODES) {
            float c0, c1, c2, c3;
            UNPACK2(c0, c1, acc2[i][0]);
            UNPACK2(c2, c3, acc2[i][1]);
            float4 o = make_float4(c0 + bv.x, c1 + bv.y, c2 + bv.z, c3 + bv.w);
            *(float4*)(out + (size_t)n * ODIM + tx * 4) = o;
        }
    }
}

// -------- host launcher --------
extern "C" void kernel_launch(void* const* d_in, const int* in_sizes, int n_in,
                              void* d_out, int out_size) {
    const float *feats = nullptr, *edge_h = nullptr, *W1 = nullptr, *b1 = nullptr;
    const float *gamma = nullptr, *bnb = nullptr, *W2 = nullptr, *b2 = nullptr, *scale = nullptr;
    const int *src = nullptr, *dst = nullptr;
    int nE = 0, nW = 0, nH = 0;
    for (int i = 0; i < n_in; i++) {
        int s = in_sizes[i];
        const void* p = d_in[i];
        if (s == NNODES * DIM) feats = (const float*)p;
        else if (s == NEDGES * DIM) edge_h = (const float*)p;
        else if (s == NEDGES) { if (nE++ == 0) src = (const int*)p; else dst = (const int*)p; }
        else if (s == DIM * HID) { if (nW++ == 0) W1 = (const float*)p; else W2 = (const float*)p; }
        else if (s == HID) {
            if (nH == 0) b1 = (const float*)p;
            else if (nH == 1) gamma = (const float*)p;
            else bnb = (const float*)p;
            nH++;
        }
        else if (s == ODIM) b2 = (const float*)p;
        else if (s == 1) scale = (const float*)p;
    }

    static bool attr_done = false;
    if (!attr_done) {
        cudaFuncSetAttribute(gemm1_kernel,
                             cudaFuncAttributeMaxDynamicSharedMemorySize,
                             G1_SMEM_BYTES);
        attr_done = true;
    }

    zero_kernel<<<(NNODES + 255) / 256, 256>>>();
    hist_kernel<<<(NEDGES / 4 + 255) / 256, 256>>>(dst);
    scan1_kernel<<<NB1, 256>>>();
    scan3_kernel<<<NB1, 256>>>();
    scatter_kernel<<<(NEDGES / 2 + 255) / 256, 256>>>(dst, src);
    gather_kernel<<<(NNODES * 16) / 256, 256>>>(feats, edge_h, scale);
    gemm1_kernel<<<(NNODES + 127) / 128, 256, G1_SMEM_BYTES>>>(W1, b1);
    gemm2_kernel<<<(NNODES + 127) / 128, 256>>>(gamma, bnb, W2, b2, (float*)d_out);
}